// round 11
// baseline (speedup 1.0000x reference)
#include <cuda_runtime.h>

// Semantics (reference dead-code eliminated):
//   r  = eye(3); tb = -mean(mkpts0, axis=1)   // mkpts0 is [3, N] row-major
// Output: 12 floats = r (identity, row-major) ++ tb.
//
// Barrier-free variant: grid=1, block=128. Warps 0-2 each reduce one row
// independently (64 float4 per lane, unrolled x8 for MLP) and write their
// own output element; warp 3 writes the constant identity. No __syncthreads,
// no shared memory, no inter-warp traffic — shortest possible critical path.

#define NTHREADS 128

__global__ void __launch_bounds__(NTHREADS, 1)
svdhead_kernel(const float* __restrict__ mkpts0,
               int n, float* __restrict__ out, int out_size) {
    int tid  = threadIdx.x;
    int lane = tid & 31;
    int warp = tid >> 5;              // 0..3

    if (warp == 3) {
        // Constant identity block + defensive tail clear.
        if (out_size >= 12) {
            if (lane == 0) {
                float4* o4 = reinterpret_cast<float4*>(out);
                o4[0] = make_float4(1.f, 0.f, 0.f, 0.f);
                o4[1] = make_float4(1.f, 0.f, 0.f, 0.f);
                out[8] = 1.f;
            }
            for (int i = 12 + lane; i < out_size; i += 32) out[i] = 0.f;
        }
        return;
    }

    int row = warp;                   // 0, 1, 2
    int nf4 = n >> 2;                 // 2048 for N=8192
    const float4* p = reinterpret_cast<const float4*>(mkpts0) + row * nf4;

    // 64 float4 per lane; 4 independent accumulators, unrolled batches of 8
    // loads so the LSU keeps ~8+ loads in flight per thread.
    float a0 = 0.f, a1 = 0.f, a2 = 0.f, a3 = 0.f;
    int j = lane;
    #pragma unroll 4
    for (; j + 3 * 32 < nf4; j += 4 * 32) {
        float4 v0 = p[j];
        float4 v1 = p[j + 32];
        float4 v2 = p[j + 64];
        float4 v3 = p[j + 96];
        a0 += (v0.x + v0.y) + (v0.z + v0.w);
        a1 += (v1.x + v1.y) + (v1.z + v1.w);
        a2 += (v2.x + v2.y) + (v2.z + v2.w);
        a3 += (v3.x + v3.y) + (v3.z + v3.w);
    }
    for (; j < nf4; j += 32) {        // remainder (not taken for N=8192)
        float4 v = p[j];
        a0 += (v.x + v.y) + (v.z + v.w);
    }
    float s = (a0 + a1) + (a2 + a3);

    #pragma unroll
    for (int off = 16; off > 0; off >>= 1)
        s += __shfl_down_sync(0xFFFFFFFFu, s, off);

    if (lane == 0 && out_size >= 12)
        out[9 + row] = -s / (float)n;
}

extern "C" void kernel_launch(void* const* d_in, const int* in_sizes, int n_in,
                              void* d_out, int out_size) {
    const float* mkpts0 = (const float*)d_in[0];
    int n = in_sizes[0] / 3;  // [3, N]
    float* out = (float*)d_out;
    svdhead_kernel<<<1, NTHREADS>>>(mkpts0, n, out, out_size);
}